// round 1
// baseline (speedup 1.0000x reference)
#include <cuda_runtime.h>
#include <math.h>

// Problem dims (fixed by the dataset)
#define BB 8
#define SS 512
#define EE 2048
#define HH 2048
#define MM (BB*SS)   // 4096 rows

// -------- scratch (no allocation allowed -> __device__ globals) --------
__device__ float g_XQ[(size_t)MM * EE];   // quantized activations (fp32 values)
__device__ float g_WgT[(size_t)EE * HH];  // W_g transposed
__device__ float g_F [(size_t)MM * HH];
__device__ float g_C [(size_t)MM * HH];
__device__ float g_G [(size_t)MM * HH];
__device__ float g_CG[(size_t)MM * HH];

// ======================= 1) rms_norm + act_quant =======================
// one block (256 threads) per row of 2048
__global__ __launch_bounds__(256) void quant_kernel(
    const float* __restrict__ x, const float* __restrict__ rms_scale)
{
    const int row = blockIdx.x;
    const float* xr = x + (size_t)row * EE;
    float* xo = g_XQ + (size_t)row * EE;
    const int tid = threadIdx.x;

    __shared__ float red_ss[8];
    __shared__ float red_mx[8];
    __shared__ float bcast[2];

    float v[8];
    float ss = 0.f;
#pragma unroll
    for (int i = 0; i < 8; i++) {
        v[i] = xr[tid + i * 256];
        ss += v[i] * v[i];
    }
#pragma unroll
    for (int o = 16; o; o >>= 1) ss += __shfl_xor_sync(0xffffffffu, ss, o);
    if ((tid & 31) == 0) red_ss[tid >> 5] = ss;
    __syncthreads();
    if (tid == 0) {
        float t = 0.f;
#pragma unroll
        for (int w = 0; w < 8; w++) t += red_ss[w];
        bcast[0] = 1.0f / sqrtf(t / (float)EE + 1e-5f);
    }
    __syncthreads();
    const float rms = bcast[0];

    float mx = 0.f;
#pragma unroll
    for (int i = 0; i < 8; i++) {
        v[i] = v[i] * rms * rms_scale[tid + i * 256];
        mx = fmaxf(mx, fabsf(v[i]));
    }
#pragma unroll
    for (int o = 16; o; o >>= 1) mx = fmaxf(mx, __shfl_xor_sync(0xffffffffu, mx, o));
    if ((tid & 31) == 0) red_mx[tid >> 5] = mx;
    __syncthreads();
    if (tid == 0) {
        float t = 0.f;
#pragma unroll
        for (int w = 0; w < 8; w++) t = fmaxf(t, red_mx[w]);
        float s = 127.0f / (t + 1e-5f);
        s = fminf(fmaxf(s, 0.001f), 1000.0f);
        bcast[1] = s;
    }
    __syncthreads();
    const float s = bcast[1];
    const float inv_s = 1.0f / s;
#pragma unroll
    for (int i = 0; i < 8; i++) {
        float q = rintf(s * v[i]);            // ties-to-even, matches jnp.round
        q = fminf(fmaxf(q, -128.0f), 127.0f);
        xo[tid + i * 256] = q * inv_s;
    }
}

// ======================= 2) transpose W_g =======================
__global__ __launch_bounds__(256) void transpose_kernel(const float* __restrict__ in)
{
    __shared__ float tile[32][33];
    int xI = blockIdx.x * 32 + threadIdx.x;
    int yI = blockIdx.y * 32 + threadIdx.y;
#pragma unroll
    for (int j = 0; j < 32; j += 8)
        tile[threadIdx.y + j][threadIdx.x] = in[(size_t)(yI + j) * EE + xI];
    __syncthreads();
    xI = blockIdx.y * 32 + threadIdx.x;
    yI = blockIdx.x * 32 + threadIdx.y;
#pragma unroll
    for (int j = 0; j < 32; j += 8)
        g_WgT[(size_t)(yI + j) * EE + xI] = tile[threadIdx.x][threadIdx.y + j];
}

// ======================= 3) fused 4-way GEMM + activation =======================
// blockIdx.z: 0 -> F = sigmoid(XQ@Wf + bf)
//             1 -> C = silu   (XQ@Wc + bc)
//             2 -> G = sigmoid(XQ@Wg + bg)
//             3 -> CG= sigmoid(X @WgT)
__global__ __launch_bounds__(256, 2) void gemm4_kernel(
    const float* __restrict__ X,
    const float* __restrict__ Wf, const float* __restrict__ Wc,
    const float* __restrict__ Wg,
    const float* __restrict__ bf, const float* __restrict__ bc,
    const float* __restrict__ bg)
{
    const int gid = blockIdx.z;
    const float* A  = (gid == 3) ? X : g_XQ;
    const float* Bp = (gid == 0) ? Wf : (gid == 1) ? Wc : (gid == 2) ? Wg : g_WgT;

    __shared__ float As[8][128];
    __shared__ float Bs[8][128];

    const int tid = threadIdx.x;
    const int m0 = blockIdx.y * 128;
    const int n0 = blockIdx.x * 128;

    const int a_m = tid >> 1;           // 0..127
    const int a_k = (tid & 1) * 4;      // 0 or 4
    const int b_k = tid >> 5;           // 0..7
    const int b_n = (tid & 31) * 4;     // 0..124

    const int tm = (tid >> 4) * 8;
    const int tn = (tid & 15) * 8;

    float acc[8][8];
#pragma unroll
    for (int i = 0; i < 8; i++)
#pragma unroll
        for (int j = 0; j < 8; j++) acc[i][j] = 0.f;

    const float* Aptr = A  + (size_t)(m0 + a_m) * EE + a_k;
    const float* Bptr = Bp + (size_t)b_k * HH + (n0 + b_n);

    for (int k0 = 0; k0 < EE; k0 += 8) {
        float4 av = *(const float4*)(Aptr + k0);
        float4 bv = *(const float4*)(Bptr + (size_t)k0 * HH);
        As[a_k + 0][a_m] = av.x;
        As[a_k + 1][a_m] = av.y;
        As[a_k + 2][a_m] = av.z;
        As[a_k + 3][a_m] = av.w;
        *(float4*)&Bs[b_k][b_n] = bv;
        __syncthreads();
#pragma unroll
        for (int kk = 0; kk < 8; kk++) {
            float a[8], b[8];
#pragma unroll
            for (int i = 0; i < 8; i++) a[i] = As[kk][tm + i];
#pragma unroll
            for (int j = 0; j < 8; j++) b[j] = Bs[kk][tn + j];
#pragma unroll
            for (int i = 0; i < 8; i++)
#pragma unroll
                for (int j = 0; j < 8; j++)
                    acc[i][j] = fmaf(a[i], b[j], acc[i][j]);
        }
        __syncthreads();
    }

    const float* bias = (gid == 0) ? bf : (gid == 1) ? bc : (gid == 2) ? bg : nullptr;
    float* Out = (gid == 0) ? g_F : (gid == 1) ? g_C : (gid == 2) ? g_G : g_CG;

#pragma unroll
    for (int i = 0; i < 8; i++) {
        size_t orow = (size_t)(m0 + tm + i) * HH + (n0 + tn);
#pragma unroll
        for (int j = 0; j < 8; j++) {
            float v = acc[i][j];
            if (bias) v += bias[n0 + tn + j];
            float sg = 1.0f / (1.0f + expf(-v));
            Out[orow + j] = (gid == 1) ? v * sg : sg;
        }
    }
}

// ======================= 4) elementwise recurrence =======================
// one thread per (b,h); serial over t. All loads coalesced across h.
__global__ __launch_bounds__(256) void scan_kernel(
    const float* __restrict__ X, float* __restrict__ out)
{
    const int idx = blockIdx.x * blockDim.x + threadIdx.x; // 0..16383
    const int b = idx >> 11;
    const int h = idx & 2047;
    float hh = 0.f;
    size_t base = ((size_t)b * SS) * HH + h;
#pragma unroll 4
    for (int t = 0; t < SS; t++, base += HH) {
        float f  = g_F [base];
        float c  = g_C [base];
        float g  = g_G [base];
        float cg = g_CG[base];
        float xv = X[base];
        float hn = f * hh + (1.f - f) * c;
        out[base] = g * hn;
        hh = cg * xv + (1.f - cg) * hn;
    }
}

// ======================= launch =======================
extern "C" void kernel_launch(void* const* d_in, const int* in_sizes, int n_in,
                              void* d_out, int out_size)
{
    const float* x         = (const float*)d_in[0];
    const float* rms_scale = (const float*)d_in[1];
    const float* W_f       = (const float*)d_in[2];
    const float* W_c       = (const float*)d_in[3];
    const float* W_g       = (const float*)d_in[4];
    const float* b_f       = (const float*)d_in[5];
    const float* b_c       = (const float*)d_in[6];
    const float* b_g       = (const float*)d_in[7];
    float* out = (float*)d_out;

    // 1) quantized activations for all B*S rows
    quant_kernel<<<MM, 256>>>(x, rms_scale);

    // 2) W_g transpose (for copy gate x @ W_g^T)
    {
        dim3 blk(32, 8);
        dim3 grd(EE / 32, HH / 32);
        transpose_kernel<<<grd, blk>>>(W_g);
    }

    // 3) the four big GEMMs with fused activations
    {
        dim3 blk(256);
        dim3 grd(HH / 128, MM / 128, 4);
        gemm4_kernel<<<grd, blk>>>(x, W_f, W_c, W_g, b_f, b_c, b_g);
    }

    // 4) sequential (elementwise-only) recurrence
    scan_kernel<<<(BB * HH) / 256, 256>>>(x, out);
}

// round 3
// speedup vs baseline: 4.0849x; 4.0849x over previous
#include <cuda_runtime.h>
#include <cuda_bf16.h>
#include <math.h>
#include <stdint.h>

// Problem dims (fixed by the dataset)
#define BB 8
#define SS 512
#define EE 2048
#define HH 2048
#define MM (BB*SS)   // 4096 rows

// ---------------- scratch (__device__ globals; no allocation allowed) ----------------
__device__ __nv_bfloat16 g_Aq [(size_t)MM * EE];        // integer q as bf16 (exact)
__device__ float         g_invs[MM];                    // 1/s per row
__device__ __nv_bfloat16 g_Acg[(size_t)MM * 2 * EE];    // [hi | lo] split of x
__device__ __nv_bfloat16 g_Bf [(size_t)HH * EE];        // W_f^T  (B[n][k] = W[k][n])
__device__ __nv_bfloat16 g_Bc [(size_t)HH * EE];        // W_c^T
__device__ __nv_bfloat16 g_Bg [(size_t)HH * EE];        // W_g^T
__device__ __nv_bfloat16 g_Bcg[(size_t)HH * 2 * EE];    // [W_g | W_g] (already [N,K])
__device__ float g_F [(size_t)MM * HH];
__device__ float g_C [(size_t)MM * HH];
__device__ float g_G [(size_t)MM * HH];
__device__ float g_CG[(size_t)MM * HH];

// ---------------- helpers ----------------
__device__ __forceinline__ uint32_t smem_u32(const void* p) {
    uint32_t a;
    asm("{ .reg .u64 t; cvta.to.shared.u64 t, %1; cvt.u32.u64 %0, t; }" : "=r"(a) : "l"(p));
    return a;
}
#define CP_ASYNC16(smem, gmem) \
    asm volatile("cp.async.cg.shared.global [%0], [%1], 16;" :: "r"((uint32_t)(smem)), "l"(gmem) : "memory")
#define CP_COMMIT() asm volatile("cp.async.commit_group;" ::: "memory")
#define CP_WAIT(n)  asm volatile("cp.async.wait_group %0;" :: "n"(n) : "memory")

#define LDSM4(r0, r1, r2, r3, addr) \
    asm volatile("ldmatrix.sync.aligned.m8n8.x4.shared.b16 {%0,%1,%2,%3}, [%4];" \
        : "=r"(r0), "=r"(r1), "=r"(r2), "=r"(r3) : "r"(addr))

#define MMA16816(d, a, b0, b1) \
    asm volatile("mma.sync.aligned.m16n8k16.row.col.f32.bf16.bf16.f32 " \
        "{%0,%1,%2,%3}, {%4,%5,%6,%7}, {%8,%9}, {%0,%1,%2,%3};" \
        : "+f"((d)[0]), "+f"((d)[1]), "+f"((d)[2]), "+f"((d)[3]) \
        : "r"((a)[0]), "r"((a)[1]), "r"((a)[2]), "r"((a)[3]), "r"(b0), "r"(b1))

#define SWZ(o) ((o) ^ ((((uint32_t)(o)) >> 3) & 0x70))

// FMA-only sigmoid: exp2 via poly + bit-assembled exponent; reciprocal via Newton.
// rel err ~1e-6, no MUFU.
__device__ __forceinline__ float fast_sigmoid(float v) {
    float t = v * 1.4426950408889634f;
    t = fminf(fmaxf(t, -126.0f), 126.0f);
    float fi = rintf(t);
    float f = t - fi;
    float p = 1.3333558146428443e-3f;
    p = fmaf(p, f, 9.6181291976126507e-3f);
    p = fmaf(p, f, 5.5504108664821580e-2f);
    p = fmaf(p, f, 2.4022650695910071e-1f);
    p = fmaf(p, f, 6.9314718055994531e-1f);
    p = fmaf(p, f, 1.0f);
    int ei = (int)fi;
    float e = p * __int_as_float((ei + 127) << 23);   // e = exp(v)
    float a = 1.0f + e;
    float r = __int_as_float(0x7EF311C3 - __float_as_int(a));
    r = r * fmaf(-a, r, 2.0f);
    r = r * fmaf(-a, r, 2.0f);
    r = r * fmaf(-a, r, 2.0f);
    return e * r;
}

// ======================= 1) rms_norm + act_quant (writes integer q as bf16) =======================
__global__ __launch_bounds__(256) void quant_kernel(
    const float* __restrict__ x, const float* __restrict__ rms_scale)
{
    const int row = blockIdx.x;
    const float* xr = x + (size_t)row * EE;
    __nv_bfloat16* xo = g_Aq + (size_t)row * EE;
    const int tid = threadIdx.x;

    __shared__ float red_ss[8];
    __shared__ float red_mx[8];
    __shared__ float bcast[2];

    float v[8];
    float ss = 0.f;
#pragma unroll
    for (int i = 0; i < 8; i++) { v[i] = xr[tid + i * 256]; ss += v[i] * v[i]; }
#pragma unroll
    for (int o = 16; o; o >>= 1) ss += __shfl_xor_sync(0xffffffffu, ss, o);
    if ((tid & 31) == 0) red_ss[tid >> 5] = ss;
    __syncthreads();
    if (tid == 0) {
        float t = 0.f;
#pragma unroll
        for (int w = 0; w < 8; w++) t += red_ss[w];
        bcast[0] = 1.0f / sqrtf(t / (float)EE + 1e-5f);
    }
    __syncthreads();
    const float rms = bcast[0];

    float mx = 0.f;
#pragma unroll
    for (int i = 0; i < 8; i++) {
        v[i] = v[i] * rms * rms_scale[tid + i * 256];
        mx = fmaxf(mx, fabsf(v[i]));
    }
#pragma unroll
    for (int o = 16; o; o >>= 1) mx = fmaxf(mx, __shfl_xor_sync(0xffffffffu, mx, o));
    if ((tid & 31) == 0) red_mx[tid >> 5] = mx;
    __syncthreads();
    if (tid == 0) {
        float t = 0.f;
#pragma unroll
        for (int w = 0; w < 8; w++) t = fmaxf(t, red_mx[w]);
        float s = 127.0f / (t + 1e-5f);
        s = fminf(fmaxf(s, 0.001f), 1000.0f);
        bcast[1] = s;
        g_invs[row] = 1.0f / s;
    }
    __syncthreads();
    const float s = bcast[1];
#pragma unroll
    for (int i = 0; i < 8; i++) {
        float q = rintf(s * v[i]);                       // ties-to-even == jnp.round
        q = fminf(fmaxf(q, -128.0f), 127.0f);
        xo[tid + i * 256] = __float2bfloat16(q);          // exact
    }
}

// ======================= 2) x -> split bf16 [hi | lo] =======================
__global__ __launch_bounds__(256) void split_kernel(const float* __restrict__ x)
{
    size_t i = (size_t)blockIdx.x * 256 + threadIdx.x;   // over MM*EE
    float v = x[i];
    __nv_bfloat16 hi = __float2bfloat16(v);
    float lo = v - __bfloat162float(hi);
    size_t m = i / EE, k = i % EE;
    g_Acg[m * (2 * EE) + k]      = hi;
    g_Acg[m * (2 * EE) + EE + k] = __float2bfloat16(lo);
}

// ======================= 3) weight transpose + bf16 convert =======================
__global__ __launch_bounds__(256) void wtrans_kernel(
    const float* __restrict__ Wf, const float* __restrict__ Wc, const float* __restrict__ Wg)
{
    const float* in = (blockIdx.z == 0) ? Wf : (blockIdx.z == 1) ? Wc : Wg;
    __nv_bfloat16* out = (blockIdx.z == 0) ? g_Bf : (blockIdx.z == 1) ? g_Bc : g_Bg;
    __shared__ float tile[32][33];
    int xI = blockIdx.x * 32 + threadIdx.x;  // H index (contig in input)
    int yI = blockIdx.y * 32 + threadIdx.y;  // E index
#pragma unroll
    for (int j = 0; j < 32; j += 8)
        tile[threadIdx.y + j][threadIdx.x] = in[(size_t)(yI + j) * HH + xI];
    __syncthreads();
    xI = blockIdx.y * 32 + threadIdx.x;      // E index (contig in output)
    yI = blockIdx.x * 32 + threadIdx.y;      // H index
#pragma unroll
    for (int j = 0; j < 32; j += 8)
        out[(size_t)(yI + j) * EE + xI] = __float2bfloat16(tile[threadIdx.x][threadIdx.y + j]);
}

// W_g already [H, E] = [N, K]; duplicate along K for the split GEMM
__global__ __launch_bounds__(256) void wcg_kernel(const float* __restrict__ Wg)
{
    size_t i = (size_t)blockIdx.x * 256 + threadIdx.x;   // over HH*EE
    size_t n = i / EE, k = i % EE;
    __nv_bfloat16 v = __float2bfloat16(Wg[i]);
    g_Bcg[n * (2 * EE) + k]      = v;
    g_Bcg[n * (2 * EE) + EE + k] = v;
}

// ======================= 4) mma.sync bf16 GEMM, fused epilogue =======================
// blockIdx.z: 0 F=sigmoid(q@Bf*inv_s+bf) 1 C=silu 2 G=sigmoid 3 CG=sigmoid(x@Wg^T)
#define STAGES 3
#define STAGE_BYTES 32768                       // 16KB A + 16KB B (128 rows x 128B)
#define GEMM_SMEM (STAGES * STAGE_BYTES)        // 96 KB

__global__ void __launch_bounds__(256, 1) gemm_mma_kernel(
    const float* __restrict__ bfp, const float* __restrict__ bcp, const float* __restrict__ bgp)
{
    extern __shared__ __align__(1024) char smem[];
    const uint32_t sb = smem_u32(smem);
    const int tid = threadIdx.x, wid = tid >> 5, lid = tid & 31;
    const int gid = blockIdx.z;
    const int m0 = blockIdx.x * 128, n0 = blockIdx.y * 128;
    const int K = (gid == 3) ? 2 * EE : EE;
    const int NC = K / 64;
    const size_t Kz = (size_t)K;

    const __nv_bfloat16* A = (gid == 3) ? g_Acg : g_Aq;
    const __nv_bfloat16* B = (gid == 0) ? g_Bf : (gid == 1) ? g_Bc : (gid == 2) ? g_Bg : g_Bcg;

    const int wm = (wid >> 2) * 64;   // warp m offset (0/64)
    const int wn = (wid & 3) * 32;    // warp n offset (0/32/64/96)

    // stage loader: 64-K chunk c -> slot s. 2048 x 16B chunks over 256 threads.
#define LOAD_STAGE(c, s) do { \
        uint32_t _sa = sb + (s) * STAGE_BYTES; \
        uint32_t _sbB = _sa + 16384; \
        _Pragma("unroll") \
        for (int j = 0; j < 4; j++) { \
            int idx = tid + j * 256; int row = idx >> 3; int c16 = idx & 7; \
            const char* ga = (const char*)A + ((size_t)(m0 + row) * Kz + (size_t)(c) * 64) * 2 + c16 * 16; \
            CP_ASYNC16(_sa + SWZ(row * 128 + c16 * 16), ga); \
        } \
        _Pragma("unroll") \
        for (int j = 0; j < 4; j++) { \
            int idx = tid + j * 256; int row = idx >> 3; int c16 = idx & 7; \
            const char* gb = (const char*)B + ((size_t)(n0 + row) * Kz + (size_t)(c) * 64) * 2 + c16 * 16; \
            CP_ASYNC16(_sbB + SWZ(row * 128 + c16 * 16), gb); \
        } \
        CP_COMMIT(); \
    } while (0)

    float acc[4][4][4];
#pragma unroll
    for (int i = 0; i < 4; i++)
#pragma unroll
        for (int j = 0; j < 4; j++)
#pragma unroll
            for (int q = 0; q < 4; q++) acc[i][j][q] = 0.f;

    LOAD_STAGE(0, 0);
    LOAD_STAGE(1, 1);
    LOAD_STAGE(2, 2);

    for (int c = 0; c < NC; c++) {
        CP_WAIT(2);
        __syncthreads();
        const int s = c % 3;
        const uint32_t sa = sb + s * STAGE_BYTES;
        const uint32_t sbB = sa + 16384;

#pragma unroll
        for (int ks = 0; ks < 4; ks++) {
            uint32_t a[4][4], b[2][4];
#pragma unroll
            for (int mt = 0; mt < 4; mt++) {
                int row = wm + mt * 16 + (lid & 15);
                uint32_t addr = sa + SWZ(row * 128 + ks * 32 + (lid >> 4) * 16);
                LDSM4(a[mt][0], a[mt][1], a[mt][2], a[mt][3], addr);
            }
#pragma unroll
            for (int nt2 = 0; nt2 < 2; nt2++) {
                int row = wn + nt2 * 16 + (lid & 7) + ((lid >> 4) & 1) * 8;
                uint32_t addr = sbB + SWZ(row * 128 + ks * 32 + ((lid >> 3) & 1) * 16);
                LDSM4(b[nt2][0], b[nt2][1], b[nt2][2], b[nt2][3], addr);
            }
#pragma unroll
            for (int mt = 0; mt < 4; mt++)
#pragma unroll
                for (int nt = 0; nt < 4; nt++) {
                    const uint32_t* bb = b[nt >> 1];
                    int p = (nt & 1) * 2;
                    MMA16816(acc[mt][nt], a[mt], bb[p], bb[p + 1]);
                }
        }
        __syncthreads();
        if (c + 3 < NC) { LOAD_STAGE(c + 3, (c + 3) % 3); } else { CP_COMMIT(); }
    }

    // -------- epilogue (no MUFU) --------
    const float* bias = (gid == 0) ? bfp : (gid == 1) ? bcp : (gid == 2) ? bgp : nullptr;
    float* Out = (gid == 0) ? g_F : (gid == 1) ? g_C : (gid == 2) ? g_G : g_CG;

    float invA[4][2];
#pragma unroll
    for (int mt = 0; mt < 4; mt++) {
        int r = m0 + wm + mt * 16 + (lid >> 2);
        invA[mt][0] = (gid < 3) ? g_invs[r]     : 1.0f;
        invA[mt][1] = (gid < 3) ? g_invs[r + 8] : 1.0f;
    }
    float2 biasv[4];
#pragma unroll
    for (int nt = 0; nt < 4; nt++) {
        int cb = n0 + wn + nt * 8 + (lid & 3) * 2;
        biasv[nt].x = bias ? bias[cb]     : 0.f;
        biasv[nt].y = bias ? bias[cb + 1] : 0.f;
    }

#pragma unroll
    for (int mt = 0; mt < 4; mt++) {
        int r0 = m0 + wm + mt * 16 + (lid >> 2);
#pragma unroll
        for (int nt = 0; nt < 4; nt++) {
            int col = n0 + wn + nt * 8 + (lid & 3) * 2;
            float v00 = fmaf(acc[mt][nt][0], invA[mt][0], biasv[nt].x);
            float v01 = fmaf(acc[mt][nt][1], invA[mt][0], biasv[nt].y);
            float v10 = fmaf(acc[mt][nt][2], invA[mt][1], biasv[nt].x);
            float v11 = fmaf(acc[mt][nt][3], invA[mt][1], biasv[nt].y);
            float s00 = fast_sigmoid(v00), s01 = fast_sigmoid(v01);
            float s10 = fast_sigmoid(v10), s11 = fast_sigmoid(v11);
            float2 o0, o1;
            if (gid == 1) { o0 = make_float2(v00 * s00, v01 * s01); o1 = make_float2(v10 * s10, v11 * s11); }
            else          { o0 = make_float2(s00, s01);             o1 = make_float2(s10, s11); }
            *(float2*)&Out[(size_t)r0 * HH + col]       = o0;
            *(float2*)&Out[(size_t)(r0 + 8) * HH + col] = o1;
        }
    }
}

// ======================= 5) elementwise recurrence =======================
__global__ __launch_bounds__(128) void scan_kernel(
    const float* __restrict__ X, float* __restrict__ out)
{
    const int idx = blockIdx.x * 128 + threadIdx.x;  // 0..16383
    const int b = idx >> 11;
    const int h = idx & 2047;
    float hh = 0.f;
    size_t base = ((size_t)b * SS) * HH + h;
#pragma unroll 16
    for (int t = 0; t < SS; t++, base += HH) {
        float f  = __ldg(&g_F [base]);
        float c  = __ldg(&g_C [base]);
        float g  = __ldg(&g_G [base]);
        float cg = __ldg(&g_CG[base]);
        float xv = __ldg(&X[base]);
        float hn = f * hh + (1.f - f) * c;
        out[base] = g * hn;
        hh = cg * xv + (1.f - cg) * hn;
    }
}

// ======================= launch =======================
extern "C" void kernel_launch(void* const* d_in, const int* in_sizes, int n_in,
                              void* d_out, int out_size)
{
    const float* x         = (const float*)d_in[0];
    const float* rms_scale = (const float*)d_in[1];
    const float* W_f       = (const float*)d_in[2];
    const float* W_c       = (const float*)d_in[3];
    const float* W_g       = (const float*)d_in[4];
    const float* b_f       = (const float*)d_in[5];
    const float* b_c       = (const float*)d_in[6];
    const float* b_g       = (const float*)d_in[7];
    float* out = (float*)d_out;

    static int attr_done = 0;
    if (!attr_done) {
        cudaFuncSetAttribute(gemm_mma_kernel, cudaFuncAttributeMaxDynamicSharedMemorySize, GEMM_SMEM);
        attr_done = 1;
    }

    quant_kernel<<<MM, 256>>>(x, rms_scale);
    split_kernel<<<(size_t)MM * EE / 256, 256>>>(x);
    {
        dim3 blk(32, 8), grd(HH / 32, EE / 32, 3);
        wtrans_kernel<<<grd, blk>>>(W_f, W_c, W_g);
    }
    wcg_kernel<<<(size_t)HH * EE / 256, 256>>>(W_g);
    {
        dim3 grd(MM / 128, HH / 128, 4);   // m fastest -> B tiles L2-resident per wave
        gemm_mma_kernel<<<grd, 256, GEMM_SMEM>>>(b_f, b_c, b_g);
    }
    scan_kernel<<<(BB * HH) / 128, 128>>>(x, out);
}